// round 16
// baseline (speedup 1.0000x reference)
#include <cuda_runtime.h>
#include <cstddef>

#define BB 32
#define EE 256
#define SS 512
#define NVOCAB 10000
#define NBLK 128
#define NTHR 256

// SMEM layout (floats), strides padded for bank spread + 16B alignment
#define WSTR 516
#define HSTR 260
#define VSTR 520

#define OFF_WG   0
#define OFF_WHH  (OFF_WG + 8*WSTR)          // 4128
#define OFF_W2   (OFF_WHH + 8*HSTR)         // 6208
#define OFF_S1   (OFF_W2 + 2*HSTR)          // 6728
#define OFF_S2   (OFF_S1 + 8)
#define OFF_BIAS (OFF_S2 + 8)
#define OFF_V    (OFF_BIAS + 8)             // 6752
#define OFF_H    (OFF_V + 32*VSTR)          // 23392
#define SMEM_FLOATS (OFF_H + 32*HSTR)       // 31712
#define SMEM_BYTES (SMEM_FLOATS * 4)        // 126848

__device__ float g_y[SS*BB*EE];     // outs [t][b][k]  (also next-step feed)
__device__ float g_h[BB*EE];
__device__ float g_ctx[BB*EE];      // enc_proj
__device__ float g_base[BB*EE];     // ctx @ w_outp[:, :E]^T
__device__ unsigned g_barcnt;
__device__ unsigned g_bargen;

__device__ __forceinline__ float2 fma2(float2 a, float2 b, float2 c) {
    float2 d;
    asm("fma.rn.f32x2 %0, %1, %2, %3;"
        : "=l"(*reinterpret_cast<unsigned long long*>(&d))
        : "l"(*reinterpret_cast<const unsigned long long*>(&a)),
          "l"(*reinterpret_cast<const unsigned long long*>(&b)),
          "l"(*reinterpret_cast<const unsigned long long*>(&c)));
    return d;
}

__device__ __forceinline__ float sigm(float x) {
    return 1.0f / (1.0f + __expf(-x));
}

// Sense-reversing grid barrier. All NBLK blocks are guaranteed co-resident
// (1 CTA/SM, NBLK=128 <= 148 SMs).
__device__ __forceinline__ void gridbar() {
    __threadfence();          // every thread's global writes visible before arrive
    __syncthreads();
    if (threadIdx.x == 0) {
        unsigned gen = atomicAdd(&g_bargen, 0u);
        if (atomicAdd(&g_barcnt, 1u) == NBLK - 1) {
            atomicExch(&g_barcnt, 0u);
            __threadfence();
            atomicAdd(&g_bargen, 1u);
        } else {
            while (atomicAdd(&g_bargen, 0u) == gen) { __nanosleep(64); }
        }
    }
    __syncthreads();
}

__global__ void __launch_bounds__(NTHR) decoder_persistent(
    const int*   __restrict__ tokens,     // [B,S]
    const float* __restrict__ enc,        // [B,E]
    const float* __restrict__ embed,      // [VOCAB,E]
    const float* __restrict__ w_ih,       // [4E,2E]
    const float* __restrict__ w_hh,       // [4E,E]
    const float* __restrict__ b_ih,       // [4E]
    const float* __restrict__ b_hh,       // [4E]
    const float* __restrict__ ln_g,       // [2E]
    const float* __restrict__ ln_b,       // [2E]
    const float* __restrict__ w_enc,      // [E,E]
    const float* __restrict__ w_outp)     // [E,2E]
{
    extern __shared__ float sm[];
    const int tid  = threadIdx.x;
    const int bid  = blockIdx.x;
    const int c0   = 2 * bid;        // first cell / out-column owned by this block
    const int b    = tid >> 3;       // batch row 0..31
    const int q    = tid & 7;
    const int cl   = q >> 2;         // cell-local (0..1) == kl in phase B
    const int gate = q & 3;          // gate i/f/g/o  == quarter in phase B
    const int lane = tid & 31;

    // ---- load per-block weight slices into SMEM (once) ----
    for (int idx = tid; idx < 8 * 512; idx += NTHR) {
        int qq = idx >> 9, m = idx & 511;
        int r = (qq & 3) * 256 + c0 + (qq >> 2);
        sm[OFF_WG + qq * WSTR + m] = w_ih[(size_t)r * 512 + m] * ln_g[m];
    }
    for (int idx = tid; idx < 8 * 256; idx += NTHR) {
        int qq = idx >> 8, m = idx & 255;
        int r = (qq & 3) * 256 + c0 + (qq >> 2);
        sm[OFF_WHH + qq * HSTR + m] = w_hh[(size_t)r * 256 + m];
    }
    for (int idx = tid; idx < 2 * 256; idx += NTHR) {
        int kl = idx >> 8, m = idx & 255;
        sm[OFF_W2 + kl * HSTR + m] = w_outp[(size_t)(c0 + kl) * 512 + 256 + m];
    }
    __syncthreads();
    if (tid < 8) {
        int r = (tid & 3) * 256 + c0 + (tid >> 2);
        float s1 = 0.0f, s2 = 0.0f;
        for (int m = 0; m < 512; m++) {
            s1 += sm[OFF_WG + tid * WSTR + m];
            s2 += w_ih[(size_t)r * 512 + m] * ln_b[m];
        }
        sm[OFF_S1 + tid]   = s1;
        sm[OFF_S2 + tid]   = s2;
        sm[OFF_BIAS + tid] = b_ih[r] + b_hh[r];
    }
    __syncthreads();

    // ---- prologue: enc_proj = enc @ w_enc^T ----
    {
        const float4* A4 = (const float4*)(enc + b * EE + gate * 64);
        const float4* W4 = (const float4*)(w_enc + (size_t)(c0 + cl) * EE + gate * 64);
        float acc = 0.0f;
        #pragma unroll
        for (int i = 0; i < 16; i++) {
            float4 a = __ldg(A4 + i), w = __ldg(W4 + i);
            acc += a.x * w.x + a.y * w.y + a.z * w.z + a.w * w.w;
        }
        acc += __shfl_xor_sync(~0u, acc, 1);
        acc += __shfl_xor_sync(~0u, acc, 2);
        if (gate == 0) __stcg(&g_ctx[b * EE + c0 + cl], acc);
    }
    gridbar();
    // ---- prologue: base = ctx @ w_outp[:, :E]^T ----
    {
        const float4* A4 = (const float4*)(g_ctx + b * EE + gate * 64);
        const float4* W4 = (const float4*)(w_outp + (size_t)(c0 + cl) * 512 + gate * 64);
        float acc = 0.0f;
        #pragma unroll
        for (int i = 0; i < 16; i++) {
            float4 a = __ldcg(A4 + i);
            float4 w = __ldg(W4 + i);
            acc += a.x * w.x + a.y * w.y + a.z * w.z + a.w * w.w;
        }
        acc += __shfl_xor_sync(~0u, acc, 1);
        acc += __shfl_xor_sync(~0u, acc, 2);
        if (gate == 0) __stcg(&g_base[b * EE + c0 + cl], acc);
    }
    gridbar();

    // hoisted loop-invariants
    const float s1q   = sm[OFF_S1 + q];
    const float s2q   = sm[OFF_S2 + q];
    const float biasq = sm[OFF_BIAS + q];
    const float my_base = __ldcg(&g_base[b * EE + c0 + cl]);
    float c_reg = 0.0f;   // cell state, lives in registers for whole sequence

    for (int t = 0; t < SS; t++) {
        // ---- stage v = [x_t | feed] and h into SMEM ----
        for (int idx = tid; idx < 2048; idx += NTHR) {
            int sb = idx >> 6;     // batch row
            int j  = idx & 63;     // float4 index within 256 floats
            int tok = __ldg(&tokens[sb * SS + t]);
            float4 xv = ((const float4*)(embed + (size_t)tok * EE))[j];
            ((float4*)(sm + OFF_V + sb * VSTR))[j] = xv;
            float4 fv;
            if (t == 0) fv = make_float4(0.f, 0.f, 0.f, 0.f);
            else        fv = __ldcg(((const float4*)(g_y + (size_t)(t - 1) * BB * EE + sb * EE)) + j);
            ((float4*)(sm + OFF_V + sb * VSTR + 256))[j] = fv;
            float4 hv = (t == 0) ? ((const float4*)(enc + sb * EE))[j]
                                 : __ldcg(((const float4*)(g_h + sb * EE)) + j);
            ((float4*)(sm + OFF_H + sb * HSTR))[j] = hv;
        }
        __syncthreads();

        // ---- LayerNorm stats over the 512 concat values of row b ----
        float s = 0.0f, ss = 0.0f;
        {
            const float4* sv4 = (const float4*)(sm + OFF_V + b * VSTR);
            #pragma unroll
            for (int i = 0; i < 16; i++) {
                float4 v = sv4[q * 16 + i];
                s  += v.x + v.y + v.z + v.w;
                ss += v.x * v.x + v.y * v.y + v.z * v.z + v.w * v.w;
            }
            s  += __shfl_xor_sync(~0u, s, 1);  ss += __shfl_xor_sync(~0u, ss, 1);
            s  += __shfl_xor_sync(~0u, s, 2);  ss += __shfl_xor_sync(~0u, ss, 2);
            s  += __shfl_xor_sync(~0u, s, 4);  ss += __shfl_xor_sync(~0u, ss, 4);
        }
        const float mu   = s * (1.0f / 512.0f);
        const float var  = ss * (1.0f / 512.0f) - mu * mu;
        const float rstd = rsqrtf(var + 1e-5f);

        // ---- gate pre-activation: rstd*(Wg.v - mu*s1) + s2 + Whh.h + bias ----
        float2 a0 = make_float2(0.f, 0.f), a1 = make_float2(0.f, 0.f);
        {
            const float4* W4 = (const float4*)(sm + OFF_WG + q * WSTR);
            const float4* V4 = (const float4*)(sm + OFF_V + b * VSTR);
            #pragma unroll 8
            for (int i = 0; i < 128; i++) {
                float4 w = W4[i], v = V4[i];
                a0 = fma2(make_float2(w.x, w.y), make_float2(v.x, v.y), a0);
                a1 = fma2(make_float2(w.z, w.w), make_float2(v.z, v.w), a1);
            }
        }
        float2 h0 = make_float2(0.f, 0.f), h1 = make_float2(0.f, 0.f);
        {
            const float4* W4 = (const float4*)(sm + OFF_WHH + q * HSTR);
            const float4* H4 = (const float4*)(sm + OFF_H + b * HSTR);
            #pragma unroll 8
            for (int i = 0; i < 64; i++) {
                float4 w = W4[i], v = H4[i];
                h0 = fma2(make_float2(w.x, w.y), make_float2(v.x, v.y), h0);
                h1 = fma2(make_float2(w.z, w.w), make_float2(v.z, v.w), h1);
            }
        }
        const float accA = a0.x + a0.y + a1.x + a1.y;
        const float accH = h0.x + h0.y + h1.x + h1.y;
        const float gp = rstd * (accA - mu * s1q) + s2q + accH + biasq;

        // ---- LSTM cell update (gate quad exchange via shfl) ----
        const float gi = __shfl_sync(~0u, gp, lane & ~3);
        const float gf = __shfl_sync(~0u, gp, (lane & ~3) | 1);
        const float gg = __shfl_sync(~0u, gp, (lane & ~3) | 2);
        const float go = __shfl_sync(~0u, gp, (lane & ~3) | 3);
        if (gate == 0) {
            float cn = sigm(gf) * c_reg + sigm(gi) * tanhf(gg);
            c_reg = cn;
            float hn = sigm(go) * tanhf(cn);
            __stcg(&g_h[b * EE + c0 + cl], hn);
        }
        gridbar();

        // ---- phase B: out = tanh(base + h @ w_outp[:,E:]^T), also next feed ----
        {
            const float4* W4  = (const float4*)(sm + OFF_W2 + cl * HSTR);
            const float4* H4g = (const float4*)(g_h + b * EE);
            float2 p0 = make_float2(0.f, 0.f), p1 = make_float2(0.f, 0.f);
            #pragma unroll
            for (int i = 0; i < 16; i++) {
                float4 w  = W4[gate * 16 + i];
                float4 hh = __ldcg(H4g + gate * 16 + i);
                p0 = fma2(make_float2(w.x, w.y), make_float2(hh.x, hh.y), p0);
                p1 = fma2(make_float2(w.z, w.w), make_float2(hh.z, hh.w), p1);
            }
            float acc = p0.x + p0.y + p1.x + p1.y;
            acc += __shfl_xor_sync(~0u, acc, 1);
            acc += __shfl_xor_sync(~0u, acc, 2);
            if (gate == 0) {
                float o = tanhf(my_base + acc);
                __stcg(&g_y[(size_t)t * BB * EE + b * EE + c0 + cl], o);
            }
        }
        gridbar();
    }
}

// ---------------- logits GEMM: out[b*S+t][v] = y[t][b] . w_fc[v] + b_fc[v] ----
__global__ void __launch_bounds__(256) fc_gemm(
    const float* __restrict__ wfc,   // [VOCAB, E]
    const float* __restrict__ bfc,   // [VOCAB]
    float* __restrict__ out)         // [B, S, VOCAB]
{
    __shared__ float sA[16][132];
    __shared__ float sB[16][132];
    const int tid = threadIdx.x;
    const int n0  = blockIdx.x * 128;
    const int r0  = blockIdx.y * 128;
    const int bb  = r0 >> 9;       // batch of this row tile (128 | 512)
    const int t0  = r0 & 511;
    const int tx  = tid & 15, ty = tid >> 4;
    const int m_a = tid >> 2;
    const int kq  = tid & 3;

    float2 acc[8][4];
    #pragma unroll
    for (int i = 0; i < 8; i++)
        #pragma unroll
        for (int j = 0; j < 4; j++) acc[i][j] = make_float2(0.f, 0.f);

    for (int k0 = 0; k0 < 256; k0 += 16) {
        #pragma unroll
        for (int l = 0; l < 2; l++) {
            int m = m_a + l * 64;
            float4 v = *(const float4*)(g_y + (size_t)(t0 + m) * (BB * EE) + bb * EE + k0 + kq * 4);
            sA[kq * 4 + 0][m] = v.x; sA[kq * 4 + 1][m] = v.y;
            sA[kq * 4 + 2][m] = v.z; sA[kq * 4 + 3][m] = v.w;
        }
        #pragma unroll
        for (int l = 0; l < 2; l++) {
            int n = m_a + l * 64;
            int gn = n0 + n;
            float4 v = make_float4(0.f, 0.f, 0.f, 0.f);
            if (gn < NVOCAB) v = *(const float4*)(wfc + (size_t)gn * EE + k0 + kq * 4);
            sB[kq * 4 + 0][n] = v.x; sB[kq * 4 + 1][n] = v.y;
            sB[kq * 4 + 2][n] = v.z; sB[kq * 4 + 3][n] = v.w;
        }
        __syncthreads();
        #pragma unroll
        for (int k = 0; k < 16; k++) {
            float4 a03 = *(const float4*)(&sA[k][ty * 8]);
            float4 a47 = *(const float4*)(&sA[k][ty * 8 + 4]);
            float4 b01 = *(const float4*)(&sB[k][tx * 8]);
            float4 b23 = *(const float4*)(&sB[k][tx * 8 + 4]);
            float  a[8]  = {a03.x, a03.y, a03.z, a03.w, a47.x, a47.y, a47.z, a47.w};
            float2 bv[4] = {make_float2(b01.x, b01.y), make_float2(b01.z, b01.w),
                            make_float2(b23.x, b23.y), make_float2(b23.z, b23.w)};
            #pragma unroll
            for (int i = 0; i < 8; i++)
                #pragma unroll
                for (int j = 0; j < 4; j++)
                    acc[i][j] = fma2(make_float2(a[i], a[i]), bv[j], acc[i][j]);
        }
        __syncthreads();
    }

    #pragma unroll
    for (int i = 0; i < 8; i++) {
        size_t r = (size_t)(r0 + ty * 8 + i);
        #pragma unroll
        for (int j = 0; j < 4; j++) {
            int n = n0 + tx * 8 + j * 2;
            if (n < NVOCAB)     out[r * NVOCAB + n]     = acc[i][j].x + bfc[n];
            if (n + 1 < NVOCAB) out[r * NVOCAB + n + 1] = acc[i][j].y + bfc[n + 1];
        }
    }
}

extern "C" void kernel_launch(void* const* d_in, const int* in_sizes, int n_in,
                              void* d_out, int out_size) {
    (void)in_sizes; (void)n_in; (void)out_size;
    const int*   tokens = (const int*)  d_in[0];
    const float* enc    = (const float*)d_in[1];
    const float* embed  = (const float*)d_in[2];
    const float* w_ih   = (const float*)d_in[3];
    const float* w_hh   = (const float*)d_in[4];
    const float* b_ih   = (const float*)d_in[5];
    const float* b_hh   = (const float*)d_in[6];
    const float* ln_g   = (const float*)d_in[7];
    const float* ln_b   = (const float*)d_in[8];
    // d_in[9] = w_inp : dead (softmax over srclen=1 collapses attention)
    const float* w_enc  = (const float*)d_in[10];
    const float* w_outp = (const float*)d_in[11];
    const float* w_fc   = (const float*)d_in[12];
    const float* b_fc   = (const float*)d_in[13];
    float* out = (float*)d_out;

    cudaFuncSetAttribute(decoder_persistent,
                         cudaFuncAttributeMaxDynamicSharedMemorySize, SMEM_BYTES);

    decoder_persistent<<<NBLK, NTHR, SMEM_BYTES>>>(
        tokens, enc, embed, w_ih, w_hh, b_ih, b_hh, ln_g, ln_b, w_enc, w_outp);

    dim3 grid((NVOCAB + 127) / 128, (BB * SS) / 128);
    fc_gemm<<<grid, 256>>>(w_fc, b_fc, out);
}